// round 1
// baseline (speedup 1.0000x reference)
#include <cuda_runtime.h>
#include <cstdint>

#define EPS    1e-12f
#define N_     8192
#define F_     512
#define D_     64
#define C_     8192

// ---------------- device scratch (no allocations allowed) ----------------
__device__ float g_zn[N_ * D_];                 // normalized projected inputs
__device__ float g_cn[C_ * D_];                 // normalized codebook
__device__ float g_csq[C_];                     // sum(cn^2) per code
__device__ unsigned long long g_best[N_];       // packed (ordered-dist-bits<<32 | idx)
__device__ float g_rowloss[N_];                 // per-row sum (zn - codes)^2
__device__ float g_dump[N_ + 1];                // fallback sink if out layout differs

__device__ __forceinline__ float warp_sum(float v) {
    #pragma unroll
    for (int o = 16; o; o >>= 1) v += __shfl_xor_sync(0xffffffffu, v, o);
    return v;
}

// ---------------- kernel 1: zn = normalise(z @ W_in + b_in) ----------------
// warp per row: lane owns output cols {lane, lane+32}
__global__ void __launch_bounds__(256) k_zn(const float* __restrict__ z,
                                            const float* __restrict__ Win,
                                            const float* __restrict__ bin) {
    __shared__ float zs[8][F_];
    int w = threadIdx.x >> 5, lane = threadIdx.x & 31;
    int row = blockIdx.x * 8 + w;
    float* zr = zs[w];
    const float* zg = z + (size_t)row * F_;
    for (int k = lane; k < F_; k += 32) zr[k] = zg[k];
    __syncwarp();

    float a0 = bin[lane], a1 = bin[lane + 32];
    #pragma unroll 8
    for (int k = 0; k < F_; k++) {
        float zv = zr[k];
        a0 = fmaf(zv, Win[k * D_ + lane],      a0);
        a1 = fmaf(zv, Win[k * D_ + lane + 32], a1);
    }
    float s = warp_sum(a0 * a0 + a1 * a1);
    float r = rsqrtf(s * (1.0f / D_) + EPS);
    g_zn[row * D_ + lane]      = a0 * r;
    g_zn[row * D_ + lane + 32] = a1 * r;
}

// ---------------- kernel 2: cn = normalise(codebook), csq = sum(cn^2) ------
__global__ void __launch_bounds__(256) k_cn(const float* __restrict__ cb) {
    int w = threadIdx.x >> 5, lane = threadIdx.x & 31;
    int row = blockIdx.x * 8 + w;
    float v0 = cb[row * D_ + lane], v1 = cb[row * D_ + lane + 32];
    float s = warp_sum(v0 * v0 + v1 * v1);
    float r = rsqrtf(s * (1.0f / D_) + EPS);
    float c0 = v0 * r, c1 = v1 * r;
    g_cn[row * D_ + lane]      = c0;
    g_cn[row * D_ + lane + 32] = c1;
    float cs = warp_sum(c0 * c0 + c1 * c1);   // exact, matches jax's sum(cn*cn)
    if (lane == 0) g_csq[row] = cs;
}

// ---------------- kernel 3: reset argmin state (every replay!) -------------
__global__ void k_init() {
    int i = blockIdx.x * blockDim.x + threadIdx.x;
    if (i < N_) g_best[i] = 0xFFFFFFFFFFFFFFFFULL;
}

// ---------------- kernel 4: fused distance GEMM + argmin -------------------
// 128x128 output tile, K=64 fits shared in one shot. 256 threads, 8x8/thread.
// dist(n,c) = csq[c] - 2*dot(zn[n],cn[c])   (z_sq dropped: row-constant)
#define AP 132   // padded leading dim for k-major tiles (16B-aligned rows)

__global__ void __launch_bounds__(256, 2) k_dist() {
    extern __shared__ float sm[];
    float* As = sm;              // [64][AP]  As[k][r]
    float* Bs = sm + 64 * AP;    // [64][AP]  Bs[k][c]
    __shared__ unsigned long long red[128];

    int tid = threadIdx.x;
    int r0 = blockIdx.y * 128, c0 = blockIdx.x * 128;
    if (tid < 128) red[tid] = 0xFFFFFFFFFFFFFFFFULL;

    const float4* znv = (const float4*)g_zn;
    const float4* cnv = (const float4*)g_cn;
    for (int i = tid; i < 128 * 16; i += 256) {
        int r = i >> 4, kq = i & 15;
        float4 v = znv[(size_t)(r0 + r) * 16 + kq];
        float4 u = cnv[(size_t)(c0 + r) * 16 + kq];
        int k = kq * 4;
        As[(k + 0) * AP + r] = v.x; As[(k + 1) * AP + r] = v.y;
        As[(k + 2) * AP + r] = v.z; As[(k + 3) * AP + r] = v.w;
        Bs[(k + 0) * AP + r] = u.x; Bs[(k + 1) * AP + r] = u.y;
        Bs[(k + 2) * AP + r] = u.z; Bs[(k + 3) * AP + r] = u.w;
    }
    __syncthreads();

    int ty = tid >> 4, tx = tid & 15;
    const float* ap = As + ty * 8;
    const float* bp = Bs + tx * 8;

    float acc[8][8];
    #pragma unroll
    for (int i = 0; i < 8; i++)
        #pragma unroll
        for (int j = 0; j < 8; j++) acc[i][j] = 0.0f;

    #pragma unroll 4
    for (int k = 0; k < 64; k++) {
        float4 a0 = *(const float4*)(ap + k * AP);
        float4 a1 = *(const float4*)(ap + k * AP + 4);
        float4 b0 = *(const float4*)(bp + k * AP);
        float4 b1 = *(const float4*)(bp + k * AP + 4);
        float a[8] = {a0.x, a0.y, a0.z, a0.w, a1.x, a1.y, a1.z, a1.w};
        float b[8] = {b0.x, b0.y, b0.z, b0.w, b1.x, b1.y, b1.z, b1.w};
        #pragma unroll
        for (int i = 0; i < 8; i++)
            #pragma unroll
            for (int j = 0; j < 8; j++)
                acc[i][j] = fmaf(a[i], b[j], acc[i][j]);
    }

    // epilogue: per-row argmin over this thread's 8 columns, then merge
    float csq[8];
    #pragma unroll
    for (int j = 0; j < 8; j++) csq[j] = g_csq[c0 + tx * 8 + j];

    #pragma unroll
    for (int i = 0; i < 8; i++) {
        float best = 3.4e38f;
        int bi = 0;
        #pragma unroll
        for (int j = 0; j < 8; j++) {
            float d = fmaf(-2.0f, acc[i][j], csq[j]);
            if (d < best) { best = d; bi = c0 + tx * 8 + j; }   // ascending j -> first-min
        }
        unsigned int kb = __float_as_uint(best);
        kb = (kb & 0x80000000u) ? ~kb : (kb | 0x80000000u);      // total order on floats
        unsigned long long packed =
            ((unsigned long long)kb << 32) | (unsigned int)bi;   // ties -> lowest idx
        atomicMin(&red[ty * 8 + i], packed);
    }
    __syncthreads();
    if (tid < 128) atomicMin(&g_best[r0 + tid], red[tid]);
}

// ---------------- kernel 5: gather codes, out = codes@W_out, row loss ------
__global__ void __launch_bounds__(256) k_out(const float* __restrict__ Wout,
                                             const float* __restrict__ bout,
                                             float* __restrict__ out,
                                             float* __restrict__ idxf) {
    __shared__ float cs[8][D_];
    int w = threadIdx.x >> 5, lane = threadIdx.x & 31;
    int row = blockIdx.x * 8 + w;

    unsigned int idx = (unsigned int)(g_best[row] & 0xffffffffu);
    float c0 = g_cn[(size_t)idx * D_ + lane];
    float c1 = g_cn[(size_t)idx * D_ + lane + 32];
    cs[w][lane] = c0;
    cs[w][lane + 32] = c1;
    float d0 = g_zn[row * D_ + lane]      - c0;
    float d1 = g_zn[row * D_ + lane + 32] - c1;
    float s = warp_sum(d0 * d0 + d1 * d1);
    if (lane == 0) { g_rowloss[row] = s; idxf[row] = (float)idx; }
    __syncwarp();

    float* o = out + (size_t)row * F_;
    #pragma unroll 4
    for (int q = 0; q < 16; q++) {
        int f = lane + q * 32;
        float acc = bout[f];
        #pragma unroll 8
        for (int d = 0; d < D_; d++) acc = fmaf(cs[w][d], Wout[d * F_ + f], acc);
        o[f] = acc;
    }
}

// ---------------- kernel 6: deterministic final loss reduction -------------
__global__ void k_loss(float* __restrict__ out_loss) {
    __shared__ double red[256];
    double s = 0.0;
    for (int i = threadIdx.x; i < N_; i += 256) s += (double)g_rowloss[i];
    red[threadIdx.x] = s;
    __syncthreads();
    for (int o = 128; o; o >>= 1) {
        if (threadIdx.x < o) red[threadIdx.x] += red[threadIdx.x + o];
        __syncthreads();
    }
    if (threadIdx.x == 0)
        *out_loss = (float)(1.25 * red[0] / (double)((long long)N_ * D_));
}

// ---------------- launch ----------------
extern "C" void kernel_launch(void* const* d_in, const int* in_sizes, int n_in,
                              void* d_out, int out_size) {
    const float* z    = (const float*)d_in[0];
    const float* Win  = (const float*)d_in[1];
    const float* bin  = (const float*)d_in[2];
    const float* cb   = (const float*)d_in[3];
    const float* Wout = (const float*)d_in[4];
    const float* bout = (const float*)d_in[5];
    float* out = (float*)d_out;

    // output tuple layout: [out (N*F)] [loss (1)] [idxes as f32 (N)]
    long long expected = (long long)N_ * F_ + 1 + N_;
    float* lossp;
    float* idxp;
    if ((long long)out_size >= expected) {
        lossp = out + (size_t)N_ * F_;
        idxp  = lossp + 1;
    } else {                               // defensive: sink extras
        cudaGetSymbolAddress((void**)&lossp, g_dump);
        idxp = lossp + 1;
    }

    const int dist_smem = 2 * 64 * AP * (int)sizeof(float);
    cudaFuncSetAttribute(k_dist, cudaFuncAttributeMaxDynamicSharedMemorySize, dist_smem);

    k_cn  <<<C_ / 8, 256>>>(cb);
    k_zn  <<<N_ / 8, 256>>>(z, Win, bin);
    k_init<<<(N_ + 255) / 256, 256>>>();
    k_dist<<<dim3(C_ / 128, N_ / 128), 256, dist_smem>>>();
    k_out <<<N_ / 8, 256>>>(Wout, bout, out, idxp);
    k_loss<<<1, 256>>>(lossp);
}

// round 4
// speedup vs baseline: 1.6776x; 1.6776x over previous
#include <cuda_runtime.h>
#include <cuda_bf16.h>
#include <cstdint>
#include <cfloat>

#define EPS    1e-12f
#define N_     8192
#define F_     512
#define D_     64
#define C_     8192

// ---------------- device scratch ----------------
__device__ __align__(16) float g_zn[N_ * D_];
__device__ __align__(16) float g_cn[C_ * D_];
__device__ __align__(16) float g_csq[C_];
__device__ unsigned long long g_best[N_];
__device__ float g_rowloss[N_];
__device__ float g_dump[N_ + 1];
// bf16 3-term splits, [split][row][64] k-major
__device__ __align__(16) __nv_bfloat16 g_zb[3 * N_ * D_];
__device__ __align__(16) __nv_bfloat16 g_cb[3 * C_ * D_];

__device__ __forceinline__ float warp_sum(float v) {
    #pragma unroll
    for (int o = 16; o; o >>= 1) v += __shfl_xor_sync(0xffffffffu, v, o);
    return v;
}
__device__ __forceinline__ uint32_t smem_to_u32(const void* p) {
    uint32_t a;
    asm("{ .reg .u64 t; cvta.to.shared.u64 t, %1; cvt.u32.u64 %0, t; }" : "=r"(a) : "l"(p));
    return a;
}
__device__ __forceinline__ void cp16(uint32_t dst, const void* src) {
    asm volatile("cp.async.cg.shared.global [%0], [%1], 16;" :: "r"(dst), "l"(src));
}
#define CP_COMMIT() asm volatile("cp.async.commit_group;" ::: "memory")
#define CP_WAIT1()  asm volatile("cp.async.wait_group 1;" ::: "memory")
#define CP_WAIT0()  asm volatile("cp.async.wait_group 0;" ::: "memory")

__device__ __forceinline__ void ldsm4(uint32_t* r, uint32_t addr) {
    asm volatile("ldmatrix.sync.aligned.m8n8.x4.shared.b16 {%0,%1,%2,%3}, [%4];"
                 : "=r"(r[0]), "=r"(r[1]), "=r"(r[2]), "=r"(r[3]) : "r"(addr));
}
__device__ __forceinline__ void mma16816(float* c, const uint32_t* a,
                                         uint32_t b0, uint32_t b1) {
    asm volatile("mma.sync.aligned.m16n8k16.row.col.f32.bf16.bf16.f32 "
                 "{%0,%1,%2,%3}, {%4,%5,%6,%7}, {%8,%9}, {%0,%1,%2,%3};"
                 : "+f"(c[0]), "+f"(c[1]), "+f"(c[2]), "+f"(c[3])
                 : "r"(a[0]), "r"(a[1]), "r"(a[2]), "r"(a[3]), "r"(b0), "r"(b1));
}
#define SWZ(o) ((o) ^ (((o) >> 3) & 0x70))

// ---------------- split helper ----------------
__device__ __forceinline__ void split3(float x, __nv_bfloat16& h1, __nv_bfloat16& h2,
                                       __nv_bfloat16& h3) {
    h1 = __float2bfloat16_rn(x);
    float r1 = x - __bfloat162float(h1);
    h2 = __float2bfloat16_rn(r1);
    float r2 = r1 - __bfloat162float(h2);
    h3 = __float2bfloat16_rn(r2);
}

// ---------------- kernel 1: zn = normalise(z @ W_in + b_in) + splits -------
__global__ void __launch_bounds__(256) k_zn(const float* __restrict__ z,
                                            const float* __restrict__ Win,
                                            const float* __restrict__ bin) {
    __shared__ float zs[8][F_];
    int w = threadIdx.x >> 5, lane = threadIdx.x & 31;
    int row = blockIdx.x * 8 + w;
    float* zr = zs[w];
    const float* zg = z + (size_t)row * F_;
    for (int k = lane; k < F_; k += 32) zr[k] = zg[k];
    __syncwarp();

    float a0 = bin[lane], a1 = bin[lane + 32];
    #pragma unroll 8
    for (int k = 0; k < F_; k++) {
        float zv = zr[k];
        a0 = fmaf(zv, Win[k * D_ + lane],      a0);
        a1 = fmaf(zv, Win[k * D_ + lane + 32], a1);
    }
    float s = warp_sum(a0 * a0 + a1 * a1);
    float r = rsqrtf(s * (1.0f / D_) + EPS);
    float zn0 = a0 * r, zn1 = a1 * r;
    g_zn[row * D_ + lane]      = zn0;
    g_zn[row * D_ + lane + 32] = zn1;
    __nv_bfloat16 h1, h2, h3;
    split3(zn0, h1, h2, h3);
    g_zb[0 * N_ * D_ + row * D_ + lane] = h1;
    g_zb[1 * N_ * D_ + row * D_ + lane] = h2;
    g_zb[2 * N_ * D_ + row * D_ + lane] = h3;
    split3(zn1, h1, h2, h3);
    g_zb[0 * N_ * D_ + row * D_ + lane + 32] = h1;
    g_zb[1 * N_ * D_ + row * D_ + lane + 32] = h2;
    g_zb[2 * N_ * D_ + row * D_ + lane + 32] = h3;
}

// ---------------- kernel 2: cn + csq + splits ----------------
__global__ void __launch_bounds__(256) k_cn(const float* __restrict__ cb) {
    int w = threadIdx.x >> 5, lane = threadIdx.x & 31;
    int row = blockIdx.x * 8 + w;
    float v0 = cb[row * D_ + lane], v1 = cb[row * D_ + lane + 32];
    float s = warp_sum(v0 * v0 + v1 * v1);
    float r = rsqrtf(s * (1.0f / D_) + EPS);
    float c0 = v0 * r, c1 = v1 * r;
    g_cn[row * D_ + lane]      = c0;
    g_cn[row * D_ + lane + 32] = c1;
    float cs = warp_sum(c0 * c0 + c1 * c1);
    if (lane == 0) g_csq[row] = cs;
    __nv_bfloat16 h1, h2, h3;
    split3(c0, h1, h2, h3);
    g_cb[0 * C_ * D_ + row * D_ + lane] = h1;
    g_cb[1 * C_ * D_ + row * D_ + lane] = h2;
    g_cb[2 * C_ * D_ + row * D_ + lane] = h3;
    split3(c1, h1, h2, h3);
    g_cb[0 * C_ * D_ + row * D_ + lane + 32] = h1;
    g_cb[1 * C_ * D_ + row * D_ + lane + 32] = h2;
    g_cb[2 * C_ * D_ + row * D_ + lane + 32] = h3;
}

// ---------------- kernel 3: reset argmin state (every replay) --------------
__global__ void k_init() {
    int i = blockIdx.x * blockDim.x + threadIdx.x;
    if (i < N_) g_best[i] = 0xFFFFFFFFFFFFFFFFULL;
}

// ---------------- kernel 4: HMMA distance GEMM + argmin --------------------
// CTA: 128 rows x 2048 cols. 32 chunks of 64 cols. 256 thr, 8 warps.
// Warp w: rows w*16..w*16+15, all 64 chunk cols (8 n-tiles).
// 6-term bf16 split: terms (ta,tb) = {00,10,20,01,11,02}, one fp32 acc.
#define OFF_A    0            // 3 splits x 128 x 128B = 48KB
#define OFF_B    49152        // 2 bufs x 3 splits x 64 x 128B = 48KB
#define OFF_CSQ  98304        // 2 x 64 floats
#define DIST_SMEM 98816

__device__ __forceinline__ void issue_B(uint32_t sb, int chunk, int buf,
                                        int c0, int tid) {
    const char* src_base = (const char*)g_cb;
    int colbase = c0 + chunk * 64;
    #pragma unroll
    for (int it = 0; it < 6; it++) {
        int i = tid + it * 256;
        int s = i >> 9, rem = i & 511, row = rem >> 3, seg = rem & 7;
        const char* src = src_base + ((size_t)s * C_ + colbase + row) * 128 + seg * 16;
        uint32_t off = row * 128 + seg * 16;
        cp16(sb + OFF_B + buf * 24576 + s * 8192 + SWZ(off), src);
    }
    if (tid < 16)
        cp16(sb + OFF_CSQ + buf * 256 + tid * 16,
             (const char*)g_csq + (size_t)(colbase + tid * 4) * 4);
}

__global__ void __launch_bounds__(256, 2) k_dist() {
    extern __shared__ char sm[];
    uint32_t sb = smem_to_u32(sm);
    const int tid = threadIdx.x, w = tid >> 5, lane = tid & 31;
    const int r0 = blockIdx.y * 128;
    const int c0 = blockIdx.x * 2048;

    // prologue: A (3 splits x 128 rows) + B chunk 0 + csq0
    {
        const char* src_base = (const char*)g_zb;
        #pragma unroll
        for (int it = 0; it < 12; it++) {
            int i = tid + it * 256;
            int s = i >> 10, rem = i & 1023, row = rem >> 3, seg = rem & 7;
            const char* src = src_base + ((size_t)s * N_ + r0 + row) * 128 + seg * 16;
            uint32_t off = row * 128 + seg * 16;
            cp16(sb + OFF_A + s * 16384 + SWZ(off), src);
        }
    }
    issue_B(sb, 0, 0, c0, tid);
    CP_COMMIT();
    CP_WAIT0();
    __syncthreads();

    // load A fragments once: a_frag[split][kstep][4]
    uint32_t a_frag[3][4][4];
    {
        int ml = (lane & 7) + ((lane >> 3) & 1) * 8;         // row within 16
        int kb = ((lane >> 4) & 1) * 16;                     // k-byte offset
        #pragma unroll
        for (int s = 0; s < 3; s++)
            #pragma unroll
            for (int k = 0; k < 4; k++) {
                uint32_t off = (w * 16 + ml) * 128 + k * 32 + kb;
                ldsm4(a_frag[s][k], sb + OFF_A + s * 16384 + SWZ(off));
            }
    }

    // per-thread best over its two rows (r, r+8)
    float best0 = FLT_MAX, best1 = FLT_MAX;
    int   idx0 = 0, idx1 = 0;

    // B-fragment lane addressing
    const int nl  = (lane & 7) + ((lane >> 4) & 1) * 8;      // n row within 16
    const int kbl = ((lane >> 3) & 1) * 16;                  // k-byte offset

    for (int c = 0; c < 32; c++) {
        int buf = c & 1;
        __syncthreads();                         // all warps done with chunk c-1
        if (c + 1 < 32) {
            issue_B(sb, c + 1, buf ^ 1, c0, tid);
            CP_COMMIT();
            CP_WAIT1();                          // chunk c's group retired
        } else {
            CP_WAIT0();
        }
        __syncthreads();

        float acc[8][4];
        #pragma unroll
        for (int nt = 0; nt < 8; nt++)
            #pragma unroll
            for (int j = 0; j < 4; j++) acc[nt][j] = 0.0f;

        uint32_t bbase = sb + OFF_B + buf * 24576;
        #pragma unroll
        for (int tb = 0; tb < 3; tb++) {
            #pragma unroll
            for (int k = 0; k < 4; k++) {
                #pragma unroll
                for (int np = 0; np < 4; np++) {
                    uint32_t br[4];
                    uint32_t off = (np * 16 + nl) * 128 + k * 32 + kbl;
                    ldsm4(br, bbase + tb * 8192 + SWZ(off));
                    // a-terms paired with this b split: ta < 3 - tb
                    #pragma unroll
                    for (int ta = 0; ta < 3; ta++) {
                        if (ta < 3 - tb) {
                            mma16816(acc[np * 2],     a_frag[ta][k], br[0], br[1]);
                            mma16816(acc[np * 2 + 1], a_frag[ta][k], br[2], br[3]);
                        }
                    }
                }
            }
        }

        // argmin epilogue straight from registers
        const float* cq = (const float*)(sm + OFF_CSQ + buf * 256);
        int gbase = c0 + c * 64;
        #pragma unroll
        for (int nt = 0; nt < 8; nt++) {
            int col = nt * 8 + (lane & 3) * 2;
            float cq0 = cq[col], cq1 = cq[col + 1];
            float d0 = fmaf(-2.0f, acc[nt][0], cq0);
            float d1 = fmaf(-2.0f, acc[nt][1], cq1);
            float d2 = fmaf(-2.0f, acc[nt][2], cq0);
            float d3 = fmaf(-2.0f, acc[nt][3], cq1);
            if (d0 < best0) { best0 = d0; idx0 = gbase + col; }
            if (d1 < best0) { best0 = d1; idx0 = gbase + col + 1; }
            if (d2 < best1) { best1 = d2; idx1 = gbase + col; }
            if (d3 < best1) { best1 = d3; idx1 = gbase + col + 1; }
        }
    }

    // merge across the 4 lanes sharing each row, then global atomicMin
    unsigned int k0 = __float_as_uint(best0);
    k0 = (k0 & 0x80000000u) ? ~k0 : (k0 | 0x80000000u);
    unsigned long long p0 = ((unsigned long long)k0 << 32) | (unsigned int)idx0;
    unsigned int k1 = __float_as_uint(best1);
    k1 = (k1 & 0x80000000u) ? ~k1 : (k1 | 0x80000000u);
    unsigned long long p1 = ((unsigned long long)k1 << 32) | (unsigned int)idx1;
    #pragma unroll
    for (int o = 1; o < 4; o <<= 1) {
        unsigned long long q0 = __shfl_xor_sync(0xffffffffu, p0, o);
        unsigned long long q1 = __shfl_xor_sync(0xffffffffu, p1, o);
        if (q0 < p0) p0 = q0;
        if (q1 < p1) p1 = q1;
    }
    if ((lane & 3) == 0) {
        int row = r0 + w * 16 + (lane >> 2);
        atomicMin(&g_best[row],     p0);
        atomicMin(&g_best[row + 8], p1);
    }
}

// ---------------- kernel 5: gather codes, out = codes@W_out, row loss ------
__global__ void __launch_bounds__(256) k_out(const float* __restrict__ Wout,
                                             const float* __restrict__ bout,
                                             float* __restrict__ out,
                                             float* __restrict__ idxf) {
    __shared__ float cs[8][D_];
    int w = threadIdx.x >> 5, lane = threadIdx.x & 31;
    int row = blockIdx.x * 8 + w;

    unsigned int idx = (unsigned int)(g_best[row] & 0xffffffffu);
    float c0 = g_cn[(size_t)idx * D_ + lane];
    float c1 = g_cn[(size_t)idx * D_ + lane + 32];
    cs[w][lane] = c0;
    cs[w][lane + 32] = c1;
    float d0 = g_zn[row * D_ + lane]      - c0;
    float d1 = g_zn[row * D_ + lane + 32] - c1;
    float s = warp_sum(d0 * d0 + d1 * d1);
    if (lane == 0) { g_rowloss[row] = s; idxf[row] = (float)idx; }
    __syncwarp();

    const float4* W4 = (const float4*)Wout;   // [d][128]
    const float4* b4 = (const float4*)bout;
    float4* o4 = (float4*)(out + (size_t)row * F_);
    #pragma unroll
    for (int g = 0; g < 4; g++) {
        int f4 = lane + g * 32;
        float4 acc = b4[f4];
        #pragma unroll 16
        for (int d = 0; d < D_; d++) {
            float4 wv = W4[d * 128 + f4];
            float v = cs[w][d];
            acc.x = fmaf(v, wv.x, acc.x);
            acc.y = fmaf(v, wv.y, acc.y);
            acc.z = fmaf(v, wv.z, acc.z);
            acc.w = fmaf(v, wv.w, acc.w);
        }
        o4[f4] = acc;
    }
}

// ---------------- kernel 6: deterministic final loss reduction -------------
__global__ void k_loss(float* __restrict__ out_loss) {
    __shared__ double red[256];
    double s = 0.0;
    for (int i = threadIdx.x; i < N_; i += 256) s += (double)g_rowloss[i];
    red[threadIdx.x] = s;
    __syncthreads();
    for (int o = 128; o; o >>= 1) {
        if (threadIdx.x < o) red[threadIdx.x] += red[threadIdx.x + o];
        __syncthreads();
    }
    if (threadIdx.x == 0)
        *out_loss = (float)(1.25 * red[0] / (double)((long long)N_ * D_));
}

// ---------------- launch ----------------
extern "C" void kernel_launch(void* const* d_in, const int* in_sizes, int n_in,
                              void* d_out, int out_size) {
    const float* z    = (const float*)d_in[0];
    const float* Win  = (const float*)d_in[1];
    const float* bin  = (const float*)d_in[2];
    const float* cb   = (const float*)d_in[3];
    const float* Wout = (const float*)d_in[4];
    const float* bout = (const float*)d_in[5];
    float* out = (float*)d_out;

    long long expected = (long long)N_ * F_ + 1 + N_;
    float* lossp;
    float* idxp;
    if ((long long)out_size >= expected) {
        lossp = out + (size_t)N_ * F_;
        idxp  = lossp + 1;
    } else {
        cudaGetSymbolAddress((void**)&lossp, g_dump);
        idxp = lossp + 1;
    }

    cudaFuncSetAttribute(k_dist, cudaFuncAttributeMaxDynamicSharedMemorySize, DIST_SMEM);

    k_cn  <<<C_ / 8, 256>>>(cb);
    k_zn  <<<N_ / 8, 256>>>(z, Win, bin);
    k_init<<<(N_ + 255) / 256, 256>>>();
    k_dist<<<dim3(4, N_ / 128), 256, DIST_SMEM>>>();
    k_out <<<N_ / 8, 256>>>(Wout, bout, out, idxp);
    k_loss<<<1, 256>>>(lossp);
}